// round 7
// baseline (speedup 1.0000x reference)
#include <cuda_runtime.h>
#include <cuda_bf16.h>

#define BATCH  32
#define LSEQ   1025
#define NTOK   513
#define TLEN   2048
#define EMB    384
#define TT     32            // frames per tile
#define NTILES (TLEN / TT)   // 64
#define NTH    384           // 2 frame-groups x 192 threads (2 cols each)
#define CH     64            // tokens per chunk

__device__ float4 g_tok[BATCH][NTOK];   // {center, 1/sig, coef (0 if dropped/PAD), token_id bits}
__device__ float  g_cumend[BATCH];
__device__ int    g_wlo[BATCH][NTILES];
__device__ int    g_whi[BATCH][NTILES];

// ---------------- Kernel A: merge + scan + token params + per-tile windows ----------------
__global__ void prep_kernel(const int* __restrict__ text, const int* __restrict__ durs) {
    int b = blockIdx.x;
    int i = threadIdx.x;
    __shared__ float a[NTOK];

    if (i < NTILES) { g_wlo[b][i] = NTOK; g_whi[b][i] = 0; }

    float d = 0.0f; int tx = 0;
    if (i < NTOK) {
        if (i == 0) { d = (float)durs[b * LSEQ]; tx = text[b * LSEQ]; }
        else {
            d  = (float)(durs[b * LSEQ + 2 * i - 1] + durs[b * LSEQ + 2 * i]);
            tx = text[b * LSEQ + 2 * i - 1];
        }
        a[i] = d;
    }
    __syncthreads();
    // Hillis-Steele inclusive scan
    for (int off = 1; off < NTOK; off <<= 1) {
        float v = 0.0f;
        if (i < NTOK) { v = a[i]; if (i >= off) v += a[i - off]; }
        __syncthreads();
        if (i < NTOK) a[i] = v;
        __syncthreads();
    }
    if (i < NTOK) {
        float cum  = a[i];
        float c    = cum - 0.5f * d;
        float sig  = 0.5f * d + 1e-6f;
        float invs = 1.0f / sig;
        bool  kept = (tx != 0) && (d > 0.0f);
        float coef = kept ? (0.3989422804014327f * invs) : 0.0f;
        g_tok[b][i] = make_float4(c, invs, coef, __int_as_float(tx));
        if (kept) {
            // z-cut = 5.5: dropped weights <= 2e-7 vs wsum >= 0.08 -> rel pert <= ~5e-5
            float r = 2.75f * d + 0.51f;
            int k0 = max(0, (int)ceilf((c - r - ((float)TT - 0.5f)) * (1.0f / TT)));
            int k1 = min(NTILES - 1, (int)floorf((c + r - 0.5f) * (1.0f / TT)));
            for (int k = k0; k <= k1; ++k) {
                atomicMin(&g_wlo[b][k], i);
                atomicMax(&g_whi[b][k], i + 1);
            }
        }
        if (i == NTOK - 1) g_cumend[b] = cum;
    }
}

// ---------------- Kernel B: windowed gaussian upsample ----------------
__global__ void __launch_bounds__(NTH, 2)
gauss_kernel(const float* __restrict__ emb, float* __restrict__ out) {
    const int b    = blockIdx.y;
    const int tile = blockIdx.x;
    const int t0   = tile * TT;
    const int tid  = threadIdx.x;
    const int h    = tid / 192;         // frame-group: frames [t0+16h, t0+16h+16)
    const int col  = tid - 192 * h;     // owns embedding cols 2*col, 2*col+1

    __shared__ __align__(16) float w_s[CH][TT];
    __shared__ float s_c[CH], s_is[CH], s_cf[CH];
    __shared__ int   s_tok[CH];
    __shared__ float wsum[TT], scale_s[TT];

    if (tid < TT) wsum[tid] = 0.0f;

    const int nlo = g_wlo[b][tile];
    const int nhi = g_whi[b][tile];
    const int total = max(0, nhi - nlo);

    float2 acc[TT / 2];
#pragma unroll
    for (int t = 0; t < TT / 2; ++t) acc[t] = make_float2(0.0f, 0.0f);

    const float2* embp = reinterpret_cast<const float2*>(emb);

    for (int cs = 0; cs < total; cs += CH) {
        const int cntc = min(CH, total - cs);
        __syncthreads();                 // protect s_* / w_s reuse across chunks
        if (tid < cntc) {
            float4 p = g_tok[b][nlo + cs + tid];
            s_c[tid]   = p.x;
            s_is[tid]  = p.y;
            s_cf[tid]  = p.z;
            s_tok[tid] = __float_as_int(p.w);
        }
        __syncthreads();

        // ---- phase 1: weights -> smem; per-thread register wsum (frame = tid & 31) ----
        {
            const int   myt = tid & (TT - 1);
            const float tm  = (float)(t0 + myt) + 0.5f;
            float wl = 0.0f;
            for (int idx = tid; idx < cntc * TT; idx += NTH) {
                int nl = idx >> 5;
                float z = (tm - s_c[nl]) * s_is[nl];
                float w = s_cf[nl] * __expf(-0.5f * z * z);
                w_s[nl][myt] = w;
                wl += w;
            }
            if (wl != 0.0f) atomicAdd(&wsum[myt], wl);
        }
        __syncthreads();

        // ---- phase 2: acc[m] += w[m] * emb[tok][2col..2col+1], 4-token unroll ----
        int u = 0;
        for (; u + 4 <= cntc; u += 4) {
            float2 e0 = embp[s_tok[u + 0] * (EMB / 2) + col];
            float2 e1 = embp[s_tok[u + 1] * (EMB / 2) + col];
            float2 e2 = embp[s_tok[u + 2] * (EMB / 2) + col];
            float2 e3 = embp[s_tok[u + 3] * (EMB / 2) + col];
#pragma unroll
            for (int k = 0; k < 4; ++k) {
                float2 ev = (k == 0) ? e0 : (k == 1) ? e1 : (k == 2) ? e2 : e3;
                const float4* wp = reinterpret_cast<const float4*>(&w_s[u + k][16 * h]);
#pragma unroll
                for (int j = 0; j < 4; ++j) {
                    float4 w4 = wp[j];
                    acc[4 * j + 0].x += w4.x * ev.x;  acc[4 * j + 0].y += w4.x * ev.y;
                    acc[4 * j + 1].x += w4.y * ev.x;  acc[4 * j + 1].y += w4.y * ev.y;
                    acc[4 * j + 2].x += w4.z * ev.x;  acc[4 * j + 2].y += w4.z * ev.y;
                    acc[4 * j + 3].x += w4.w * ev.x;  acc[4 * j + 3].y += w4.w * ev.y;
                }
            }
        }
        for (; u < cntc; ++u) {
            float2 ev = embp[s_tok[u] * (EMB / 2) + col];
            const float4* wp = reinterpret_cast<const float4*>(&w_s[u][16 * h]);
#pragma unroll
            for (int j = 0; j < 4; ++j) {
                float4 w4 = wp[j];
                acc[4 * j + 0].x += w4.x * ev.x;  acc[4 * j + 0].y += w4.x * ev.y;
                acc[4 * j + 1].x += w4.y * ev.x;  acc[4 * j + 1].y += w4.y * ev.y;
                acc[4 * j + 2].x += w4.z * ev.x;  acc[4 * j + 2].y += w4.z * ev.y;
                acc[4 * j + 3].x += w4.w * ev.x;  acc[4 * j + 3].y += w4.w * ev.y;
            }
        }
    }
    __syncthreads();

    // ---- normalization scales ----
    if (tid < TT) {
        float tmv = (float)(t0 + tid) + 0.5f;
        scale_s[tid] = (tmv < g_cumend[b]) ? (1.0f / (wsum[tid] + 1e-6f)) : 0.0f;
    }
    __syncthreads();

    // ---- normalize + store (float2, coalesced per frame) ----
    float2* outp = reinterpret_cast<float2*>(out);
    size_t base = ((size_t)(b * TLEN + t0 + 16 * h)) * (EMB / 2) + col;
#pragma unroll
    for (int m = 0; m < TT / 2; ++m) {
        float s = scale_s[16 * h + m];
        outp[base + (size_t)m * (EMB / 2)] = make_float2(acc[m].x * s, acc[m].y * s);
    }
}

extern "C" void kernel_launch(void* const* d_in, const int* in_sizes, int n_in,
                              void* d_out, int out_size) {
    const int*   text = (const int*)d_in[0];
    const int*   durs = (const int*)d_in[1];
    const float* emb  = (const float*)d_in[2];
    float* out = (float*)d_out;

    prep_kernel<<<BATCH, 544>>>(text, durs);
    dim3 grid(NTILES, BATCH);
    gauss_kernel<<<grid, NTH>>>(emb, out);
}

// round 8
// speedup vs baseline: 1.1643x; 1.1643x over previous
#include <cuda_runtime.h>
#include <cuda_bf16.h>

#define BATCH  32
#define LSEQ   1025
#define NTOK   513
#define TLEN   2048
#define EMB    384
#define TT     16            // frames per tile
#define NTILES (TLEN / TT)   // 128
#define NTH    192           // threads per block; each owns 2 embedding cols
#define KMAX   64            // max tokens per tile list

__device__ float4 g_list[BATCH][NTILES][KMAX]; // compacted per-tile token params
__device__ int    g_cnt[BATCH][NTILES];
__device__ float  g_cumend[BATCH];

// ---------------- Kernel A: merge + scan + token params + per-tile compacted lists ----------------
__global__ void prep_kernel(const int* __restrict__ text, const int* __restrict__ durs) {
    int b = blockIdx.x;
    int i = threadIdx.x;
    __shared__ float a[NTOK];

    if (i < NTILES) g_cnt[b][i] = 0;

    float d = 0.0f; int tx = 0;
    if (i < NTOK) {
        if (i == 0) { d = (float)durs[b * LSEQ]; tx = text[b * LSEQ]; }
        else {
            d  = (float)(durs[b * LSEQ + 2 * i - 1] + durs[b * LSEQ + 2 * i]);
            tx = text[b * LSEQ + 2 * i - 1];
        }
        a[i] = d;
    }
    __syncthreads();
    // Hillis-Steele inclusive scan (also orders g_cnt zeroing before appends)
    for (int off = 1; off < NTOK; off <<= 1) {
        float v = 0.0f;
        if (i < NTOK) { v = a[i]; if (i >= off) v += a[i - off]; }
        __syncthreads();
        if (i < NTOK) a[i] = v;
        __syncthreads();
    }
    if (i < NTOK) {
        float cum  = a[i];
        float c    = cum - 0.5f * d;
        float sig  = 0.5f * d + 1e-6f;
        float invs = 1.0f / sig;
        bool  kept = (tx != 0) && (d > 0.0f);
        if (kept) {
            float coef = 0.3989422804014327f * invs;
            // z-cut = 5.5: dropped weights <= 2e-7 vs wsum >= 0.08 -> rel pert <= ~5e-5
            float r = 2.75f * d + 0.51f;
            int k0 = max(0, (int)ceilf((c - r - ((float)TT - 0.5f)) * (1.0f / TT)));
            int k1 = min(NTILES - 1, (int)floorf((c + r - 0.5f) * (1.0f / TT)));
            float4 e = make_float4(c, invs, coef, __int_as_float(tx));
            for (int k = k0; k <= k1; ++k) {
                int s = atomicAdd(&g_cnt[b][k], 1);
                if (s < KMAX) g_list[b][k][s] = e;
            }
        }
        if (i == NTOK - 1) g_cumend[b] = cum;
    }
}

// ---------------- Kernel B: windowed gaussian upsample ----------------
__global__ void __launch_bounds__(NTH, 4)
gauss_kernel(const float* __restrict__ emb, float* __restrict__ out) {
    const int b    = blockIdx.y;
    const int tile = blockIdx.x;
    const int t0   = tile * TT;
    const int tid  = threadIdx.x;       // owns embedding cols 2*tid, 2*tid+1

    __shared__ __align__(16) float w_s[KMAX][TT];
    __shared__ float s_c[KMAX], s_is[KMAX], s_cf[KMAX];
    __shared__ int   s_tok[KMAX];
    __shared__ float wsum[TT], scale_s[TT];

    // ---- concurrent independent loads: count + my list entry ----
    const int cnt_raw = g_cnt[b][tile];          // L2 broadcast
    float4 p;
    if (tid < KMAX) p = g_list[b][tile][tid];    // independent LDG, overlaps cnt load
    const int cnt = min(cnt_raw, KMAX);

    if (tid < TT) wsum[tid] = 0.0f;
    if (tid < cnt) {
        s_c[tid]   = p.x;
        s_is[tid]  = p.y;
        s_cf[tid]  = p.z;
        s_tok[tid] = __float_as_int(p.w);
    }
    __syncthreads();

    // ---- phase 1: weights -> smem; per-thread register wsum (frame fixed = tid & 15) ----
    {
        const int   myt = tid & (TT - 1);
        const float tm  = (float)(t0 + myt) + 0.5f;
        float wl = 0.0f;
        for (int idx = tid; idx < cnt * TT; idx += NTH) {
            int nl = idx >> 4;
            float z = (tm - s_c[nl]) * s_is[nl];
            float w = s_cf[nl] * __expf(-0.5f * z * z);
            w_s[nl][myt] = w;
            wl += w;
        }
        if (wl != 0.0f) atomicAdd(&wsum[myt], wl);
    }
    __syncthreads();

    if (tid < TT) {
        float tmv = (float)(t0 + tid) + 0.5f;
        scale_s[tid] = (tmv < g_cumend[b]) ? (1.0f / (wsum[tid] + 1e-6f)) : 0.0f;
    }

    // ---- phase 2: acc[t] += w[t] * emb[tok][2tid..2tid+1], 4-token unroll, MLP=4 ----
    float2 acc[TT];
#pragma unroll
    for (int t = 0; t < TT; ++t) acc[t] = make_float2(0.0f, 0.0f);

    const float2* embp = reinterpret_cast<const float2*>(emb);

    int cs = 0;
    for (; cs + 4 <= cnt; cs += 4) {
        float2 e0 = embp[s_tok[cs + 0] * (EMB / 2) + tid];
        float2 e1 = embp[s_tok[cs + 1] * (EMB / 2) + tid];
        float2 e2 = embp[s_tok[cs + 2] * (EMB / 2) + tid];
        float2 e3 = embp[s_tok[cs + 3] * (EMB / 2) + tid];
#pragma unroll
        for (int u = 0; u < 4; ++u) {
            float2 ev = (u == 0) ? e0 : (u == 1) ? e1 : (u == 2) ? e2 : e3;
            const float4* wp = reinterpret_cast<const float4*>(w_s[cs + u]);
#pragma unroll
            for (int j = 0; j < TT / 4; ++j) {
                float4 w4 = wp[j];
                acc[4 * j + 0].x += w4.x * ev.x;  acc[4 * j + 0].y += w4.x * ev.y;
                acc[4 * j + 1].x += w4.y * ev.x;  acc[4 * j + 1].y += w4.y * ev.y;
                acc[4 * j + 2].x += w4.z * ev.x;  acc[4 * j + 2].y += w4.z * ev.y;
                acc[4 * j + 3].x += w4.w * ev.x;  acc[4 * j + 3].y += w4.w * ev.y;
            }
        }
    }
    for (; cs < cnt; ++cs) {
        float2 ev = embp[s_tok[cs] * (EMB / 2) + tid];
        const float4* wp = reinterpret_cast<const float4*>(w_s[cs]);
#pragma unroll
        for (int j = 0; j < TT / 4; ++j) {
            float4 w4 = wp[j];
            acc[4 * j + 0].x += w4.x * ev.x;  acc[4 * j + 0].y += w4.x * ev.y;
            acc[4 * j + 1].x += w4.y * ev.x;  acc[4 * j + 1].y += w4.y * ev.y;
            acc[4 * j + 2].x += w4.z * ev.x;  acc[4 * j + 2].y += w4.z * ev.y;
            acc[4 * j + 3].x += w4.w * ev.x;  acc[4 * j + 3].y += w4.w * ev.y;
        }
    }
    __syncthreads();   // scale_s ready

    // ---- normalize + store (float2, coalesced per frame) ----
    float2* outp = reinterpret_cast<float2*>(out);
    size_t base = ((size_t)(b * TLEN + t0)) * (EMB / 2) + tid;
#pragma unroll
    for (int tt = 0; tt < TT; ++tt) {
        float s = scale_s[tt];
        outp[base + (size_t)tt * (EMB / 2)] = make_float2(acc[tt].x * s, acc[tt].y * s);
    }
}

extern "C" void kernel_launch(void* const* d_in, const int* in_sizes, int n_in,
                              void* d_out, int out_size) {
    const int*   text = (const int*)d_in[0];
    const int*   durs = (const int*)d_in[1];
    const float* emb  = (const float*)d_in[2];
    float* out = (float*)d_out;

    prep_kernel<<<BATCH, 544>>>(text, durs);
    dim3 grid(NTILES, BATCH);
    gauss_kernel<<<grid, NTH>>>(emb, out);
}

// round 9
// speedup vs baseline: 1.1732x; 1.0077x over previous
#include <cuda_runtime.h>
#include <cuda_bf16.h>

#define BATCH  32
#define LSEQ   1025
#define NTOK   513
#define TLEN   2048
#define EMB    384
#define TT     16            // frames per tile
#define NTILES (TLEN / TT)   // 128
#define NTH    192           // threads per block; each owns 2 embedding cols
#define KMAX   64            // max tokens per tile list
#define PWARPS 17            // prep warps (544 threads)

__device__ float4 g_list[BATCH][NTILES][KMAX]; // compacted per-tile token params
__device__ int    g_cnt[BATCH][NTILES];
__device__ float  g_cumend[BATCH];

// ---------------- Kernel A: merge + warp-shuffle scan + per-tile compacted lists ----------------
__global__ void prep_kernel(const int* __restrict__ text, const int* __restrict__ durs) {
    const int b    = blockIdx.x;
    const int i    = threadIdx.x;
    const int lane = i & 31;
    const int wid  = i >> 5;

    __shared__ float wpart[PWARPS];

    if (i < NTILES) g_cnt[b][i] = 0;

    float d = 0.0f; int tx = 0;
    if (i < NTOK) {
        if (i == 0) { d = (float)durs[b * LSEQ]; tx = text[b * LSEQ]; }
        else {
            d  = (float)(durs[b * LSEQ + 2 * i - 1] + durs[b * LSEQ + 2 * i]);
            tx = text[b * LSEQ + 2 * i - 1];
        }
    }

    // warp-level inclusive scan
    float v = d;
#pragma unroll
    for (int off = 1; off < 32; off <<= 1) {
        float n = __shfl_up_sync(0xffffffffu, v, off);
        if (lane >= off) v += n;
    }
    if (lane == 31) wpart[wid] = v;
    __syncthreads();            // also orders g_cnt zeroing before appends
    if (wid == 0) {
        float s = (lane < PWARPS) ? wpart[lane] : 0.0f;
#pragma unroll
        for (int off = 1; off < 32; off <<= 1) {
            float n = __shfl_up_sync(0xffffffffu, s, off);
            if (lane >= off) s += n;
        }
        if (lane < PWARPS) wpart[lane] = s;
    }
    __syncthreads();
    const float cum = v + (wid > 0 ? wpart[wid - 1] : 0.0f);

    if (i < NTOK) {
        float c    = cum - 0.5f * d;
        float sig  = 0.5f * d + 1e-6f;
        float invs = 1.0f / sig;
        bool  kept = (tx != 0) && (d > 0.0f);
        if (kept) {
            float coef = 0.3989422804014327f * invs;
            // z-cut = 5.5: dropped weights <= 2e-7 vs wsum >= 0.08 -> rel pert <= ~5e-5
            float r = 2.75f * d + 0.51f;
            int k0 = max(0, (int)ceilf((c - r - ((float)TT - 0.5f)) * (1.0f / TT)));
            int k1 = min(NTILES - 1, (int)floorf((c + r - 0.5f) * (1.0f / TT)));
            float4 e = make_float4(c, invs, coef, __int_as_float(tx));
            for (int k = k0; k <= k1; ++k) {
                int s = atomicAdd(&g_cnt[b][k], 1);
                if (s < KMAX) g_list[b][k][s] = e;
            }
        }
        if (i == NTOK - 1) g_cumend[b] = cum;
    }
}

// ---------------- Kernel B: windowed gaussian upsample ----------------
__global__ void __launch_bounds__(NTH, 4)
gauss_kernel(const float* __restrict__ emb, float* __restrict__ out) {
    const int b    = blockIdx.y;
    const int tile = blockIdx.x;
    const int t0   = tile * TT;
    const int tid  = threadIdx.x;       // owns embedding cols 2*tid, 2*tid+1

    __shared__ __align__(16) float w_s[KMAX][TT];
    __shared__ float s_c[KMAX], s_is[KMAX], s_cf[KMAX];
    __shared__ int   s_tok[KMAX];
    __shared__ float wsum[TT], scale_s[TT];

    // ---- concurrent independent loads: count + my list entry ----
    const int cnt_raw = g_cnt[b][tile];          // L2 broadcast
    float4 p;
    if (tid < KMAX) p = g_list[b][tile][tid];    // independent LDG, overlaps cnt load
    const int cnt = min(cnt_raw, KMAX);

    if (tid < TT) wsum[tid] = 0.0f;
    if (tid < cnt) {
        s_c[tid]   = p.x;
        s_is[tid]  = p.y;
        s_cf[tid]  = p.z;
        s_tok[tid] = __float_as_int(p.w);
    }
    __syncthreads();

    // ---- prefetch first 4 emb rows (hides L2 latency behind phase 1) ----
    const float2* embp = reinterpret_cast<const float2*>(emb);
    float2 e0, e1, e2, e3;
    const bool full4 = (cnt >= 4);
    if (full4) {
        e0 = embp[s_tok[0] * (EMB / 2) + tid];
        e1 = embp[s_tok[1] * (EMB / 2) + tid];
        e2 = embp[s_tok[2] * (EMB / 2) + tid];
        e3 = embp[s_tok[3] * (EMB / 2) + tid];
    }

    // ---- phase 1: weights -> smem; per-thread register wsum (frame fixed = tid & 15) ----
    {
        const int   myt = tid & (TT - 1);
        const float tm  = (float)(t0 + myt) + 0.5f;
        float wl = 0.0f;
        for (int idx = tid; idx < cnt * TT; idx += NTH) {
            int nl = idx >> 4;
            float z = (tm - s_c[nl]) * s_is[nl];
            float w = s_cf[nl] * __expf(-0.5f * z * z);
            w_s[nl][myt] = w;
            wl += w;
        }
        if (wl != 0.0f) atomicAdd(&wsum[myt], wl);
    }
    __syncthreads();

    if (tid < TT) {
        float tmv = (float)(t0 + tid) + 0.5f;
        scale_s[tid] = (tmv < g_cumend[b]) ? (1.0f / (wsum[tid] + 1e-6f)) : 0.0f;
    }

    // ---- phase 2: acc[t] += w[t] * emb[tok][2tid..2tid+1], 4-token unroll, MLP=4 ----
    float2 acc[TT];
#pragma unroll
    for (int t = 0; t < TT; ++t) acc[t] = make_float2(0.0f, 0.0f);

    int cs = 0;
    for (; cs + 4 <= cnt; cs += 4) {
        if (cs > 0) {
            e0 = embp[s_tok[cs + 0] * (EMB / 2) + tid];
            e1 = embp[s_tok[cs + 1] * (EMB / 2) + tid];
            e2 = embp[s_tok[cs + 2] * (EMB / 2) + tid];
            e3 = embp[s_tok[cs + 3] * (EMB / 2) + tid];
        }
#pragma unroll
        for (int u = 0; u < 4; ++u) {
            float2 ev = (u == 0) ? e0 : (u == 1) ? e1 : (u == 2) ? e2 : e3;
            const float4* wp = reinterpret_cast<const float4*>(w_s[cs + u]);
#pragma unroll
            for (int j = 0; j < TT / 4; ++j) {
                float4 w4 = wp[j];
                acc[4 * j + 0].x += w4.x * ev.x;  acc[4 * j + 0].y += w4.x * ev.y;
                acc[4 * j + 1].x += w4.y * ev.x;  acc[4 * j + 1].y += w4.y * ev.y;
                acc[4 * j + 2].x += w4.z * ev.x;  acc[4 * j + 2].y += w4.z * ev.y;
                acc[4 * j + 3].x += w4.w * ev.x;  acc[4 * j + 3].y += w4.w * ev.y;
            }
        }
    }
    for (; cs < cnt; ++cs) {
        float2 ev = embp[s_tok[cs] * (EMB / 2) + tid];
        const float4* wp = reinterpret_cast<const float4*>(w_s[cs]);
#pragma unroll
        for (int j = 0; j < TT / 4; ++j) {
            float4 w4 = wp[j];
            acc[4 * j + 0].x += w4.x * ev.x;  acc[4 * j + 0].y += w4.x * ev.y;
            acc[4 * j + 1].x += w4.y * ev.x;  acc[4 * j + 1].y += w4.y * ev.y;
            acc[4 * j + 2].x += w4.z * ev.x;  acc[4 * j + 2].y += w4.z * ev.y;
            acc[4 * j + 3].x += w4.w * ev.x;  acc[4 * j + 3].y += w4.w * ev.y;
        }
    }
    __syncthreads();   // scale_s ready

    // ---- normalize + store (float2, coalesced per frame) ----
    float2* outp = reinterpret_cast<float2*>(out);
    size_t base = ((size_t)(b * TLEN + t0)) * (EMB / 2) + tid;
#pragma unroll
    for (int tt = 0; tt < TT; ++tt) {
        float s = scale_s[tt];
        outp[base + (size_t)tt * (EMB / 2)] = make_float2(acc[tt].x * s, acc[tt].y * s);
    }
}

extern "C" void kernel_launch(void* const* d_in, const int* in_sizes, int n_in,
                              void* d_out, int out_size) {
    const int*   text = (const int*)d_in[0];
    const int*   durs = (const int*)d_in[1];
    const float* emb  = (const float*)d_in[2];
    float* out = (float*)d_out;

    prep_kernel<<<BATCH, 544>>>(text, durs);
    dim3 grid(NTILES, BATCH);
    gauss_kernel<<<grid, NTH>>>(emb, out);
}

// round 10
// speedup vs baseline: 1.2482x; 1.0639x over previous
#include <cuda_runtime.h>
#include <cuda_bf16.h>

#define BATCH  32
#define LSEQ   1025
#define NTOK   513
#define TLEN   2048
#define EMB    384
#define TT     16            // frames per tile
#define NTILES (TLEN / TT)   // 128
#define NTH    192           // threads per block; each owns 2 embedding cols
#define KMAX   64            // max tokens per tile list
#define PWARPS 17            // prep warps (544 threads)

__device__ float4 g_list[BATCH][NTILES][KMAX]; // compacted per-tile token params
__device__ int    g_cnt[BATCH][NTILES];
__device__ float  g_cumend[BATCH];

// ---------------- Kernel A: merge + warp-shuffle scan + per-tile compacted lists ----------------
__global__ void prep_kernel(const int* __restrict__ text, const int* __restrict__ durs) {
    const int b    = blockIdx.x;
    const int i    = threadIdx.x;
    const int lane = i & 31;
    const int wid  = i >> 5;

    __shared__ float wpart[PWARPS];
    __shared__ int   s_cnt[NTILES];

    if (i < NTILES) s_cnt[i] = 0;

    float d = 0.0f; int tx = 0;
    if (i < NTOK) {
        if (i == 0) { d = (float)durs[b * LSEQ]; tx = text[b * LSEQ]; }
        else {
            d  = (float)(durs[b * LSEQ + 2 * i - 1] + durs[b * LSEQ + 2 * i]);
            tx = text[b * LSEQ + 2 * i - 1];
        }
    }

    // warp-level inclusive scan
    float v = d;
#pragma unroll
    for (int off = 1; off < 32; off <<= 1) {
        float n = __shfl_up_sync(0xffffffffu, v, off);
        if (lane >= off) v += n;
    }
    if (lane == 31) wpart[wid] = v;
    __syncthreads();            // also orders s_cnt zeroing before appends
    if (wid == 0) {
        float s = (lane < PWARPS) ? wpart[lane] : 0.0f;
#pragma unroll
        for (int off = 1; off < 32; off <<= 1) {
            float n = __shfl_up_sync(0xffffffffu, s, off);
            if (lane >= off) s += n;
        }
        if (lane < PWARPS) wpart[lane] = s;
    }
    __syncthreads();
    const float cum = v + (wid > 0 ? wpart[wid - 1] : 0.0f);

    if (i < NTOK) {
        float c    = cum - 0.5f * d;
        float sig  = 0.5f * d + 1e-6f;
        float invs = 1.0f / sig;
        bool  kept = (tx != 0) && (d > 0.0f);
        if (kept) {
            float coef = 0.3989422804014327f * invs;
            // z-cut = 5.5: dropped weights <= 2e-7 vs wsum >= 0.08 -> rel pert <= ~5e-5
            float r = 2.75f * d + 0.51f;
            int k0 = max(0, (int)ceilf((c - r - ((float)TT - 0.5f)) * (1.0f / TT)));
            int k1 = min(NTILES - 1, (int)floorf((c + r - 0.5f) * (1.0f / TT)));
            float4 e = make_float4(c, invs, coef, __int_as_float(tx));
            for (int k = k0; k <= k1; ++k) {
                int s = atomicAdd(&s_cnt[k], 1);   // fast smem atomic
                if (s < KMAX) g_list[b][k][s] = e; // fire-and-forget STG.128
            }
        }
        if (i == NTOK - 1) g_cumend[b] = cum;
    }
    __syncthreads();
    if (i < NTILES) g_cnt[b][i] = min(s_cnt[i], KMAX);
}

// ---------------- Kernel B: windowed gaussian upsample ----------------
__global__ void __launch_bounds__(NTH, 4)
gauss_kernel(const float* __restrict__ emb, float* __restrict__ out) {
    const int b    = blockIdx.y;
    const int tile = blockIdx.x;
    const int t0   = tile * TT;
    const int tid  = threadIdx.x;       // owns embedding cols 2*tid, 2*tid+1

    __shared__ __align__(16) float w_s[KMAX][TT];
    __shared__ float s_c[KMAX], s_is[KMAX], s_cf[KMAX];
    __shared__ int   s_tok[KMAX];
    __shared__ float wsum[TT], scale_s[TT];

    // ---- concurrent independent loads: count + my list entry ----
    const int cnt_raw = g_cnt[b][tile];          // L2 broadcast
    float4 p;
    if (tid < KMAX) p = g_list[b][tile][tid];    // independent LDG, overlaps cnt load
    const int cnt = min(cnt_raw, KMAX);

    if (tid < TT) wsum[tid] = 0.0f;
    if (tid < cnt) {
        s_c[tid]   = p.x;
        s_is[tid]  = p.y;
        s_cf[tid]  = p.z;
        s_tok[tid] = __float_as_int(p.w);
    }
    __syncthreads();

    // ---- prefetch first 4 emb rows (hides L2 latency behind phase 1) ----
    const float2* embp = reinterpret_cast<const float2*>(emb);
    float2 e0, e1, e2, e3;
    if (cnt >= 4) {
        e0 = embp[s_tok[0] * (EMB / 2) + tid];
        e1 = embp[s_tok[1] * (EMB / 2) + tid];
        e2 = embp[s_tok[2] * (EMB / 2) + tid];
        e3 = embp[s_tok[3] * (EMB / 2) + tid];
    }

    // ---- phase 1: weights -> smem; per-thread register wsum (frame fixed = tid & 15) ----
    {
        const int   myt = tid & (TT - 1);
        const float tm  = (float)(t0 + myt) + 0.5f;
        float wl = 0.0f;
        for (int idx = tid; idx < cnt * TT; idx += NTH) {
            int nl = idx >> 4;
            float z = (tm - s_c[nl]) * s_is[nl];
            float w = s_cf[nl] * __expf(-0.5f * z * z);
            w_s[nl][myt] = w;
            wl += w;
        }
        if (wl != 0.0f) atomicAdd(&wsum[myt], wl);
    }
    __syncthreads();

    if (tid < TT) {
        float tmv = (float)(t0 + tid) + 0.5f;
        scale_s[tid] = (tmv < g_cumend[b]) ? (1.0f / (wsum[tid] + 1e-6f)) : 0.0f;
    }

    // ---- phase 2: acc[t] += w[t] * emb[tok][2tid..2tid+1], 4-token unroll, MLP=4 ----
    float2 acc[TT];
#pragma unroll
    for (int t = 0; t < TT; ++t) acc[t] = make_float2(0.0f, 0.0f);

    int cs = 0;
    for (; cs + 4 <= cnt; cs += 4) {
        if (cs > 0) {
            e0 = embp[s_tok[cs + 0] * (EMB / 2) + tid];
            e1 = embp[s_tok[cs + 1] * (EMB / 2) + tid];
            e2 = embp[s_tok[cs + 2] * (EMB / 2) + tid];
            e3 = embp[s_tok[cs + 3] * (EMB / 2) + tid];
        }
#pragma unroll
        for (int u = 0; u < 4; ++u) {
            float2 ev = (u == 0) ? e0 : (u == 1) ? e1 : (u == 2) ? e2 : e3;
            const float4* wp = reinterpret_cast<const float4*>(w_s[cs + u]);
#pragma unroll
            for (int j = 0; j < TT / 4; ++j) {
                float4 w4 = wp[j];
                acc[4 * j + 0].x += w4.x * ev.x;  acc[4 * j + 0].y += w4.x * ev.y;
                acc[4 * j + 1].x += w4.y * ev.x;  acc[4 * j + 1].y += w4.y * ev.y;
                acc[4 * j + 2].x += w4.z * ev.x;  acc[4 * j + 2].y += w4.z * ev.y;
                acc[4 * j + 3].x += w4.w * ev.x;  acc[4 * j + 3].y += w4.w * ev.y;
            }
        }
    }
    for (; cs < cnt; ++cs) {
        float2 ev = embp[s_tok[cs] * (EMB / 2) + tid];
        const float4* wp = reinterpret_cast<const float4*>(w_s[cs]);
#pragma unroll
        for (int j = 0; j < TT / 4; ++j) {
            float4 w4 = wp[j];
            acc[4 * j + 0].x += w4.x * ev.x;  acc[4 * j + 0].y += w4.x * ev.y;
            acc[4 * j + 1].x += w4.y * ev.x;  acc[4 * j + 1].y += w4.y * ev.y;
            acc[4 * j + 2].x += w4.z * ev.x;  acc[4 * j + 2].y += w4.z * ev.y;
            acc[4 * j + 3].x += w4.w * ev.x;  acc[4 * j + 3].y += w4.w * ev.y;
        }
    }
    __syncthreads();   // scale_s ready

    // ---- normalize + store (float2, coalesced per frame) ----
    float2* outp = reinterpret_cast<float2*>(out);
    size_t base = ((size_t)(b * TLEN + t0)) * (EMB / 2) + tid;
#pragma unroll
    for (int tt = 0; tt < TT; ++tt) {
        float s = scale_s[tt];
        outp[base + (size_t)tt * (EMB / 2)] = make_float2(acc[tt].x * s, acc[tt].y * s);
    }
}

extern "C" void kernel_launch(void* const* d_in, const int* in_sizes, int n_in,
                              void* d_out, int out_size) {
    const int*   text = (const int*)d_in[0];
    const int*   durs = (const int*)d_in[1];
    const float* emb  = (const float*)d_in[2];
    float* out = (float*)d_out;

    prep_kernel<<<BATCH, 544>>>(text, durs);
    dim3 grid(NTILES, BATCH);
    gauss_kernel<<<grid, NTH>>>(emb, out);
}

// round 11
// speedup vs baseline: 1.3154x; 1.0538x over previous
#include <cuda_runtime.h>
#include <cuda_bf16.h>

#define BATCH  32
#define LSEQ   1025
#define NTOK   513
#define TLEN   2048
#define EMB    384
#define TT     16            // frames per tile
#define NTILES (TLEN / TT)   // 128
#define NTH    192           // threads per block; each owns 2 embedding cols
#define KMAX   64            // max tokens per tile list
#define PWARPS 17            // prep warps (544 threads)

using u64 = unsigned long long;

__device__ float4 g_list[BATCH][NTILES][KMAX]; // compacted per-tile token params
__device__ int    g_cnt[BATCH][NTILES];
__device__ float  g_cumend[BATCH];

__device__ __forceinline__ u64 pack2(float lo, float hi) {
    u64 r; asm("mov.b64 %0, {%1,%2};" : "=l"(r) : "f"(lo), "f"(hi)); return r;
}
__device__ __forceinline__ void unpack2(u64 v, float& lo, float& hi) {
    asm("mov.b64 {%0,%1}, %2;" : "=f"(lo), "=f"(hi) : "l"(v));
}
__device__ __forceinline__ u64 ffma2(u64 a, u64 b, u64 c) {
    u64 r; asm("fma.rn.f32x2 %0, %1, %2, %3;" : "=l"(r) : "l"(a), "l"(b), "l"(c)); return r;
}
__device__ __forceinline__ u64 fmul2(u64 a, u64 b) {
    u64 r; asm("mul.rn.f32x2 %0, %1, %2;" : "=l"(r) : "l"(a), "l"(b)); return r;
}

// ---------------- Kernel A: merge + warp-shuffle scan + per-tile compacted lists ----------------
__global__ void prep_kernel(const int* __restrict__ text, const int* __restrict__ durs) {
    const int b    = blockIdx.x;
    const int i    = threadIdx.x;
    const int lane = i & 31;
    const int wid  = i >> 5;

    __shared__ float wpart[PWARPS];
    __shared__ int   s_cnt[NTILES];

    if (i < NTILES) s_cnt[i] = 0;

    float d = 0.0f; int tx = 0;
    if (i < NTOK) {
        if (i == 0) { d = (float)durs[b * LSEQ]; tx = text[b * LSEQ]; }
        else {
            d  = (float)(durs[b * LSEQ + 2 * i - 1] + durs[b * LSEQ + 2 * i]);
            tx = text[b * LSEQ + 2 * i - 1];
        }
    }

    // warp-level inclusive scan
    float v = d;
#pragma unroll
    for (int off = 1; off < 32; off <<= 1) {
        float n = __shfl_up_sync(0xffffffffu, v, off);
        if (lane >= off) v += n;
    }
    if (lane == 31) wpart[wid] = v;
    __syncthreads();            // also orders s_cnt zeroing before appends
    if (wid == 0) {
        float s = (lane < PWARPS) ? wpart[lane] : 0.0f;
#pragma unroll
        for (int off = 1; off < 32; off <<= 1) {
            float n = __shfl_up_sync(0xffffffffu, s, off);
            if (lane >= off) s += n;
        }
        if (lane < PWARPS) wpart[lane] = s;
    }
    __syncthreads();
    const float cum = v + (wid > 0 ? wpart[wid - 1] : 0.0f);

    if (i < NTOK) {
        float c    = cum - 0.5f * d;
        float sig  = 0.5f * d + 1e-6f;
        float invs = 1.0f / sig;
        bool  kept = (tx != 0) && (d > 0.0f);
        if (kept) {
            float coef = 0.3989422804014327f * invs;
            // z-cut = 5.5: dropped weights <= 2e-7 vs wsum >= 0.08 -> rel pert <= ~5e-5
            float r = 2.75f * d + 0.51f;
            int k0 = max(0, (int)ceilf((c - r - ((float)TT - 0.5f)) * (1.0f / TT)));
            int k1 = min(NTILES - 1, (int)floorf((c + r - 0.5f) * (1.0f / TT)));
            float4 e = make_float4(c, invs, coef, __int_as_float(tx));
            for (int k = k0; k <= k1; ++k) {
                int s = atomicAdd(&s_cnt[k], 1);   // fast smem atomic
                if (s < KMAX) g_list[b][k][s] = e; // fire-and-forget STG.128
            }
        }
        if (i == NTOK - 1) g_cumend[b] = cum;
    }
    __syncthreads();
    if (i < NTILES) g_cnt[b][i] = min(s_cnt[i], KMAX);
}

// ---------------- Kernel B: windowed gaussian upsample (packed f32x2 FMA) ----------------
__global__ void __launch_bounds__(NTH, 4)
gauss_kernel(const float* __restrict__ emb, float* __restrict__ out) {
    const int b    = blockIdx.y;
    const int tile = blockIdx.x;
    const int t0   = tile * TT;
    const int tid  = threadIdx.x;       // owns embedding cols 2*tid, 2*tid+1

    __shared__ __align__(16) float w_s[KMAX][TT];
    __shared__ float s_c[KMAX], s_is[KMAX], s_cf[KMAX];
    __shared__ int   s_tok[KMAX];
    __shared__ __align__(8) float wsum[TT];
    __shared__ __align__(8) float scale_s[TT];

    // ---- concurrent independent loads: count + my list entry ----
    const int cnt_raw = g_cnt[b][tile];          // L2 broadcast
    float4 p;
    if (tid < KMAX) p = g_list[b][tile][tid];    // independent LDG, overlaps cnt load
    const int cnt = min(cnt_raw, KMAX);

    if (tid < TT) wsum[tid] = 0.0f;
    if (tid < cnt) {
        s_c[tid]   = p.x;
        s_is[tid]  = p.y;
        s_cf[tid]  = p.z;
        s_tok[tid] = __float_as_int(p.w);
    }
    __syncthreads();

    // ---- prefetch first 4 emb rows (hides L2 latency behind phase 1) ----
    const float2* embp = reinterpret_cast<const float2*>(emb);
    float2 e0, e1, e2, e3;
    if (cnt >= 4) {
        e0 = embp[s_tok[0] * (EMB / 2) + tid];
        e1 = embp[s_tok[1] * (EMB / 2) + tid];
        e2 = embp[s_tok[2] * (EMB / 2) + tid];
        e3 = embp[s_tok[3] * (EMB / 2) + tid];
    }

    // ---- phase 1: weights -> smem; per-thread register wsum (frame fixed = tid & 15) ----
    {
        const int   myt = tid & (TT - 1);
        const float tm  = (float)(t0 + myt) + 0.5f;
        float wl = 0.0f;
        for (int idx = tid; idx < cnt * TT; idx += NTH) {
            int nl = idx >> 4;
            float z = (tm - s_c[nl]) * s_is[nl];
            float w = s_cf[nl] * __expf(-0.5f * z * z);
            w_s[nl][myt] = w;
            wl += w;
        }
        if (wl != 0.0f) atomicAdd(&wsum[myt], wl);
    }
    __syncthreads();

    if (tid < TT) {
        float tmv = (float)(t0 + tid) + 0.5f;
        scale_s[tid] = (tmv < g_cumend[b]) ? (1.0f / (wsum[tid] + 1e-6f)) : 0.0f;
    }

    // ---- phase 2: packed accumulation. accA = col0 over frame pairs, accB = col1 ----
    u64 accA[TT / 2], accB[TT / 2];
#pragma unroll
    for (int j = 0; j < TT / 2; ++j) { accA[j] = 0ull; accB[j] = 0ull; }

    int cs = 0;
    for (; cs + 4 <= cnt; cs += 4) {
        if (cs > 0) {
            e0 = embp[s_tok[cs + 0] * (EMB / 2) + tid];
            e1 = embp[s_tok[cs + 1] * (EMB / 2) + tid];
            e2 = embp[s_tok[cs + 2] * (EMB / 2) + tid];
            e3 = embp[s_tok[cs + 3] * (EMB / 2) + tid];
        }
#pragma unroll
        for (int u = 0; u < 4; ++u) {
            float2 ev = (u == 0) ? e0 : (u == 1) ? e1 : (u == 2) ? e2 : e3;
            u64 exA = pack2(ev.x, ev.x);
            u64 exB = pack2(ev.y, ev.y);
            const ulonglong2* wp = reinterpret_cast<const ulonglong2*>(w_s[cs + u]);
#pragma unroll
            for (int j = 0; j < TT / 4; ++j) {
                ulonglong2 wq = wp[j];     // LDS.128: frames 4j..4j+3 as two pairs
                accA[2 * j + 0] = ffma2(wq.x, exA, accA[2 * j + 0]);
                accB[2 * j + 0] = ffma2(wq.x, exB, accB[2 * j + 0]);
                accA[2 * j + 1] = ffma2(wq.y, exA, accA[2 * j + 1]);
                accB[2 * j + 1] = ffma2(wq.y, exB, accB[2 * j + 1]);
            }
        }
    }
    for (; cs < cnt; ++cs) {
        float2 ev = embp[s_tok[cs] * (EMB / 2) + tid];
        u64 exA = pack2(ev.x, ev.x);
        u64 exB = pack2(ev.y, ev.y);
        const ulonglong2* wp = reinterpret_cast<const ulonglong2*>(w_s[cs]);
#pragma unroll
        for (int j = 0; j < TT / 4; ++j) {
            ulonglong2 wq = wp[j];
            accA[2 * j + 0] = ffma2(wq.x, exA, accA[2 * j + 0]);
            accB[2 * j + 0] = ffma2(wq.x, exB, accB[2 * j + 0]);
            accA[2 * j + 1] = ffma2(wq.y, exA, accA[2 * j + 1]);
            accB[2 * j + 1] = ffma2(wq.y, exB, accB[2 * j + 1]);
        }
    }
    __syncthreads();   // scale_s ready

    // ---- normalize (packed) + store (float2 per frame, coalesced) ----
    float2* outp = reinterpret_cast<float2*>(out);
    size_t base = ((size_t)(b * TLEN + t0)) * (EMB / 2) + tid;
    const u64* sp = reinterpret_cast<const u64*>(scale_s);
#pragma unroll
    for (int j = 0; j < TT / 2; ++j) {
        u64 s2 = sp[j];                      // (scale[2j], scale[2j+1])
        u64 va = fmul2(accA[j], s2);
        u64 vb = fmul2(accB[j], s2);
        float a0, a1, b0, b1;
        unpack2(va, a0, a1);
        unpack2(vb, b0, b1);
        outp[base + (size_t)(2 * j)     * (EMB / 2)] = make_float2(a0, b0);
        outp[base + (size_t)(2 * j + 1) * (EMB / 2)] = make_float2(a1, b1);
    }
}

extern "C" void kernel_launch(void* const* d_in, const int* in_sizes, int n_in,
                              void* d_out, int out_size) {
    const int*   text = (const int*)d_in[0];
    const int*   durs = (const int*)d_in[1];
    const float* emb  = (const float*)d_in[2];
    float* out = (float*)d_out;

    prep_kernel<<<BATCH, 544>>>(text, durs);
    dim3 grid(NTILES, BATCH);
    gauss_kernel<<<grid, NTH>>>(emb, out);
}

// round 12
// speedup vs baseline: 1.3639x; 1.0369x over previous
#include <cuda_runtime.h>
#include <cuda_bf16.h>

#define BATCH  32
#define LSEQ   1025
#define NTOK   513
#define TLEN   2048
#define EMB    384
#define TT     16            // frames per tile
#define NTILES (TLEN / TT)   // 128
#define NTH    192           // threads per block; each owns 2 embedding cols
#define KMAX   64            // max tokens per tile list
#define PWARPS 17            // prep warps (544 threads)
#define GBLK   592           // persistent grid: 4 CTAs/SM x 148 SMs
#define TOTAL  (BATCH * NTILES)

using u64 = unsigned long long;

__device__ float4 g_list[BATCH][NTILES][KMAX]; // compacted per-tile token params
__device__ int    g_cnt[BATCH][NTILES];
__device__ float  g_cumend[BATCH];

__device__ __forceinline__ u64 pack2(float lo, float hi) {
    u64 r; asm("mov.b64 %0, {%1,%2};" : "=l"(r) : "f"(lo), "f"(hi)); return r;
}
__device__ __forceinline__ void unpack2(u64 v, float& lo, float& hi) {
    asm("mov.b64 {%0,%1}, %2;" : "=f"(lo), "=f"(hi) : "l"(v));
}
__device__ __forceinline__ u64 ffma2(u64 a, u64 b, u64 c) {
    u64 r; asm("fma.rn.f32x2 %0, %1, %2, %3;" : "=l"(r) : "l"(a), "l"(b), "l"(c)); return r;
}
__device__ __forceinline__ u64 fmul2(u64 a, u64 b) {
    u64 r; asm("mul.rn.f32x2 %0, %1, %2;" : "=l"(r) : "l"(a), "l"(b)); return r;
}

// ---------------- Kernel A: merge + warp-shuffle scan + per-tile compacted lists ----------------
__global__ void prep_kernel(const int* __restrict__ text, const int* __restrict__ durs) {
    const int b    = blockIdx.x;
    const int i    = threadIdx.x;
    const int lane = i & 31;
    const int wid  = i >> 5;

    __shared__ float wpart[PWARPS];
    __shared__ int   s_cnt[NTILES];

    if (i < NTILES) s_cnt[i] = 0;

    float d = 0.0f; int tx = 0;
    if (i < NTOK) {
        if (i == 0) { d = (float)durs[b * LSEQ]; tx = text[b * LSEQ]; }
        else {
            d  = (float)(durs[b * LSEQ + 2 * i - 1] + durs[b * LSEQ + 2 * i]);
            tx = text[b * LSEQ + 2 * i - 1];
        }
    }

    // warp-level inclusive scan
    float v = d;
#pragma unroll
    for (int off = 1; off < 32; off <<= 1) {
        float n = __shfl_up_sync(0xffffffffu, v, off);
        if (lane >= off) v += n;
    }
    if (lane == 31) wpart[wid] = v;
    __syncthreads();            // also orders s_cnt zeroing before appends
    if (wid == 0) {
        float s = (lane < PWARPS) ? wpart[lane] : 0.0f;
#pragma unroll
        for (int off = 1; off < 32; off <<= 1) {
            float n = __shfl_up_sync(0xffffffffu, s, off);
            if (lane >= off) s += n;
        }
        if (lane < PWARPS) wpart[lane] = s;
    }
    __syncthreads();
    const float cum = v + (wid > 0 ? wpart[wid - 1] : 0.0f);

    if (i < NTOK) {
        float c    = cum - 0.5f * d;
        float sig  = 0.5f * d + 1e-6f;
        float invs = 1.0f / sig;
        bool  kept = (tx != 0) && (d > 0.0f);
        if (kept) {
            float coef = 0.3989422804014327f * invs;
            // z-cut = 5.5: dropped weights <= 2e-7 vs wsum >= 0.08 -> rel pert <= ~5e-5
            float r = 2.75f * d + 0.51f;
            int k0 = max(0, (int)ceilf((c - r - ((float)TT - 0.5f)) * (1.0f / TT)));
            int k1 = min(NTILES - 1, (int)floorf((c + r - 0.5f) * (1.0f / TT)));
            float4 e = make_float4(c, invs, coef, __int_as_float(tx));
            for (int k = k0; k <= k1; ++k) {
                int s = atomicAdd(&s_cnt[k], 1);   // fast smem atomic
                if (s < KMAX) g_list[b][k][s] = e; // fire-and-forget STG.128
            }
        }
        if (i == NTOK - 1) g_cumend[b] = cum;
    }
    __syncthreads();
    if (i < NTILES) g_cnt[b][i] = min(s_cnt[i], KMAX);
}

// ---------------- Kernel B: persistent pipelined gaussian upsample ----------------
__global__ void __launch_bounds__(NTH, 4)
gauss_kernel(const float* __restrict__ emb, float* __restrict__ out) {
    const int tid = threadIdx.x;       // owns embedding cols 2*tid, 2*tid+1

    __shared__ __align__(16) float w_s[KMAX][TT];
    __shared__ float s_c[KMAX], s_is[KMAX], s_cf[KMAX];
    __shared__ int   s_tok[KMAX];
    __shared__ __align__(8) float wsum[TT];
    __shared__ __align__(8) float scale_s[TT];

    const float2* embp = reinterpret_cast<const float2*>(emb);
    float2* outp = reinterpret_cast<float2*>(out);

    // ---- prefetch first tile's count + list entry ----
    int g = blockIdx.x;
    int cnt_next = 0;
    float4 p_next = make_float4(0.f, 0.f, 0.f, 0.f);
    {
        const int bb = g >> 7, kk = g & (NTILES - 1);
        cnt_next = g_cnt[bb][kk];
        if (tid < KMAX) p_next = g_list[bb][kk][tid];
    }

    for (; g < TOTAL; g += GBLK) {
        const int b   = g >> 7;
        const int t0  = (g & (NTILES - 1)) * TT;
        const int cnt = min(cnt_next, KMAX);
        const float4 p = p_next;

        __syncthreads();    // previous tile fully done with smem
        if (tid < TT) wsum[tid] = 0.0f;
        if (tid < cnt) {
            s_c[tid]   = p.x;
            s_is[tid]  = p.y;
            s_cf[tid]  = p.z;
            s_tok[tid] = __float_as_int(p.w);
        }
        __syncthreads();

        // ---- issue next tile's loads (hidden behind this tile's compute) ----
        {
            const int gn = g + GBLK;
            if (gn < TOTAL) {
                const int bn = gn >> 7, kn = gn & (NTILES - 1);
                cnt_next = g_cnt[bn][kn];
                if (tid < KMAX) p_next = g_list[bn][kn][tid];
            }
        }

        // ---- phase 1: weights -> smem; per-thread register wsum (frame = tid & 15) ----
        {
            const int   myt = tid & (TT - 1);
            const float tm  = (float)(t0 + myt) + 0.5f;
            float wl = 0.0f;
            for (int idx = tid; idx < cnt * TT; idx += NTH) {
                int nl = idx >> 4;
                float z = (tm - s_c[nl]) * s_is[nl];
                float w = s_cf[nl] * __expf(-0.5f * z * z);
                w_s[nl][myt] = w;
                wl += w;
            }
            if (wl != 0.0f) atomicAdd(&wsum[myt], wl);
        }
        __syncthreads();

        if (tid < TT) {
            float tmv = (float)(t0 + tid) + 0.5f;
            scale_s[tid] = (tmv < g_cumend[b]) ? (1.0f / (wsum[tid] + 1e-6f)) : 0.0f;
        }

        // ---- phase 2: packed f32x2 accumulation, 4-token unroll, MLP=4 ----
        u64 accA[TT / 2], accB[TT / 2];
#pragma unroll
        for (int j = 0; j < TT / 2; ++j) { accA[j] = 0ull; accB[j] = 0ull; }

        int cs = 0;
        for (; cs + 4 <= cnt; cs += 4) {
            float2 e0 = embp[s_tok[cs + 0] * (EMB / 2) + tid];
            float2 e1 = embp[s_tok[cs + 1] * (EMB / 2) + tid];
            float2 e2 = embp[s_tok[cs + 2] * (EMB / 2) + tid];
            float2 e3 = embp[s_tok[cs + 3] * (EMB / 2) + tid];
#pragma unroll
            for (int u = 0; u < 4; ++u) {
                float2 ev = (u == 0) ? e0 : (u == 1) ? e1 : (u == 2) ? e2 : e3;
                u64 exA = pack2(ev.x, ev.x);
                u64 exB = pack2(ev.y, ev.y);
                const ulonglong2* wp = reinterpret_cast<const ulonglong2*>(w_s[cs + u]);
#pragma unroll
                for (int j = 0; j < TT / 4; ++j) {
                    ulonglong2 wq = wp[j];
                    accA[2 * j + 0] = ffma2(wq.x, exA, accA[2 * j + 0]);
                    accB[2 * j + 0] = ffma2(wq.x, exB, accB[2 * j + 0]);
                    accA[2 * j + 1] = ffma2(wq.y, exA, accA[2 * j + 1]);
                    accB[2 * j + 1] = ffma2(wq.y, exB, accB[2 * j + 1]);
                }
            }
        }
        for (; cs < cnt; ++cs) {
            float2 ev = embp[s_tok[cs] * (EMB / 2) + tid];
            u64 exA = pack2(ev.x, ev.x);
            u64 exB = pack2(ev.y, ev.y);
            const ulonglong2* wp = reinterpret_cast<const ulonglong2*>(w_s[cs]);
#pragma unroll
            for (int j = 0; j < TT / 4; ++j) {
                ulonglong2 wq = wp[j];
                accA[2 * j + 0] = ffma2(wq.x, exA, accA[2 * j + 0]);
                accB[2 * j + 0] = ffma2(wq.x, exB, accB[2 * j + 0]);
                accA[2 * j + 1] = ffma2(wq.y, exA, accA[2 * j + 1]);
                accB[2 * j + 1] = ffma2(wq.y, exB, accB[2 * j + 1]);
            }
        }
        __syncthreads();   // scale_s ready

        // ---- normalize (packed) + store (float2 per frame, coalesced) ----
        size_t base = ((size_t)(g * TT)) * (EMB / 2) + tid;   // b*TLEN + t0 == g*TT
        const u64* sp = reinterpret_cast<const u64*>(scale_s);
#pragma unroll
        for (int j = 0; j < TT / 2; ++j) {
            u64 s2 = sp[j];                      // (scale[2j], scale[2j+1])
            u64 va = fmul2(accA[j], s2);
            u64 vb = fmul2(accB[j], s2);
            float a0, a1, b0, b1;
            unpack2(va, a0, a1);
            unpack2(vb, b0, b1);
            outp[base + (size_t)(2 * j)     * (EMB / 2)] = make_float2(a0, b0);
            outp[base + (size_t)(2 * j + 1) * (EMB / 2)] = make_float2(a1, b1);
        }
    }
}

extern "C" void kernel_launch(void* const* d_in, const int* in_sizes, int n_in,
                              void* d_out, int out_size) {
    const int*   text = (const int*)d_in[0];
    const int*   durs = (const int*)d_in[1];
    const float* emb  = (const float*)d_in[2];
    float* out = (float*)d_out;

    prep_kernel<<<BATCH, 544>>>(text, durs);
    gauss_kernel<<<GBLK, NTH>>>(emb, out);
}